// round 11
// baseline (speedup 1.0000x reference)
#include <cuda_runtime.h>
#include <cuda_fp16.h>
#include <math.h>
#include <stdint.h>

#define Bc  2
#define Sc  2048
#define Ec  2048
#define Ac  2048
#define Hc  16
#define HDc 128

// Scratch (device globals), fp16 operands.
__device__ __half g_Q[Bc*Hc*Sc*HDc];
__device__ __half g_K[Bc*Hc*Sc*HDc];
__device__ __half g_V[Bc*Hc*Sc*HDc];
__device__ __half g_attn[Bc*Sc*Ac];          // attention out (fp16)
__device__ __half g_x_h[Bc*Sc*Ec];           // x fp16 [4096][2048]
__device__ __half g_wqkv_t[3*Ac*Ec];         // W_qkv^T fp16 [6144][2048]
__device__ __half g_wout_t[Ec*Ac];           // W_out^T fp16 [2048][2048]
__device__ float  g_cos[Sc*(HDc/2)];
__device__ float  g_sin[Sc*(HDc/2)];

// ---------------------------------------------------------------------------
__device__ __forceinline__ void mma_h(float* c, const unsigned* a, const unsigned* b) {
    asm volatile("mma.sync.aligned.m16n8k16.row.col.f32.f16.f16.f32 "
        "{%0,%1,%2,%3}, {%4,%5,%6,%7}, {%8,%9}, {%0,%1,%2,%3};"
        : "+f"(c[0]), "+f"(c[1]), "+f"(c[2]), "+f"(c[3])
        : "r"(a[0]), "r"(a[1]), "r"(a[2]), "r"(a[3]), "r"(b[0]), "r"(b[1]));
}
__device__ __forceinline__ void ldm_x4(unsigned& r0, unsigned& r1, unsigned& r2,
                                       unsigned& r3, unsigned addr) {
    asm volatile("ldmatrix.sync.aligned.m8n8.x4.shared.b16 {%0,%1,%2,%3}, [%4];"
        : "=r"(r0), "=r"(r1), "=r"(r2), "=r"(r3) : "r"(addr));
}
__device__ __forceinline__ void ldm_x4_t(unsigned& r0, unsigned& r1, unsigned& r2,
                                         unsigned& r3, unsigned addr) {
    asm volatile("ldmatrix.sync.aligned.m8n8.x4.trans.shared.b16 {%0,%1,%2,%3}, [%4];"
        : "=r"(r0), "=r"(r1), "=r"(r2), "=r"(r3) : "r"(addr));
}
__device__ __forceinline__ void cp16(void* smem_dst, const void* gsrc) {
    unsigned d = (unsigned)__cvta_generic_to_shared(smem_dst);
    asm volatile("cp.async.cg.shared.global [%0], [%1], 16;" :: "r"(d), "l"(gsrc));
}
__device__ __forceinline__ void cp_commit() { asm volatile("cp.async.commit_group;"); }
__device__ __forceinline__ unsigned smem_u32(const void* p) {
    return (unsigned)__cvta_generic_to_shared(p);
}

// ---------------------------------------------------------------------------
__global__ void rope_table_kernel() {
    int idx = blockIdx.x * blockDim.x + threadIdx.x;
    if (idx >= Sc * (HDc/2)) return;
    int pos = idx / (HDc/2);
    int j   = idx % (HDc/2);
    double inv = pow(10000.0, -((double)(2*j)) / (double)HDc);
    double a = (double)pos * inv;
    g_cos[idx] = (float)cos(a);
    g_sin[idx] = (float)sin(a);
}

__global__ void cvt_h(const float4* __restrict__ src, __half2* __restrict__ dst, int n4) {
    int i = blockIdx.x * blockDim.x + threadIdx.x;
    if (i < n4) {
        float4 v = src[i];
        dst[2*i]   = __floats2half2_rn(v.x, v.y);
        dst[2*i+1] = __floats2half2_rn(v.z, v.w);
    }
}

__global__ __launch_bounds__(256) void transpose_cvt_h(
    const float* __restrict__ src, __half* __restrict__ dst, int R, int Ccols) {
    __shared__ __half tile[32][33];
    int c0 = blockIdx.x*32, r0 = blockIdx.y*32;
    int tx = threadIdx.x & 31, ty = threadIdx.x >> 5;
    #pragma unroll
    for (int i = 0; i < 4; i++)
        tile[ty + 8*i][tx] = __float2half(src[(size_t)(r0 + ty + 8*i)*Ccols + c0 + tx]);
    __syncthreads();
    #pragma unroll
    for (int i = 0; i < 4; i++)
        dst[(size_t)(c0 + ty + 8*i)*R + r0 + tx] = tile[tx][ty + 8*i];
}

// ---------------------------------------------------------------------------
// fp16 GEMM: CTA 128x256, BK=32, 16 warps (2x8), warp tile 64x32 (identical
// per-warp layout to the 802us R7 kernel), 3-stage cp.async, ldmatrix.
// mode 1: A=g_x_h, B=g_wqkv_t -> RoPE scatter to g_Q/g_K/g_V.
// mode 0: A=g_attn, B=g_wout_t -> fp32 C.
// ---------------------------------------------------------------------------
#define AW 40                          // padded row width (halves)
#define STG_H ((128+256)*AW)           // halves per stage
#define STG_B (STG_H*2)                // bytes per stage

__global__ __launch_bounds__(512, 1) void gemm_h(
    float* __restrict__ C, int N, int K, int mode)
{
    extern __shared__ __half hs[];

    const __half* Ag = mode ? g_x_h : g_attn;
    const __half* Bg = mode ? g_wqkv_t : g_wout_t;

    int tid  = threadIdx.x;
    int warp = tid >> 5, lane = tid & 31;
    int lr = lane & 7, lq = lane >> 3;
    int g = lane >> 2, t4 = lane & 3;
    int wm = warp >> 3, wn = warp & 7;          // 2 x 8 warp grid
    int m0 = blockIdx.y * 128, n0 = blockIdx.x * 256;
    unsigned sbase = smem_u32(hs);

    float acc[4][4][4];
    #pragma unroll
    for (int i = 0; i < 4; i++)
        #pragma unroll
        for (int j = 0; j < 4; j++)
            #pragma unroll
            for (int r = 0; r < 4; r++) acc[i][j][r] = 0.f;

    int T = K / 32;

    // stage loader: A 128x32 (512 chunks), B 256x32 (1024 chunks), 512 thr
    auto load_stage = [&](int s, int kt) {
        __half* As = hs + s*STG_H;
        __half* Bs = As + 128*AW;
        {
            int c = tid;                        // 512 chunks, 1 per thread
            int row = c >> 2, kc = (c & 3) * 8;
            cp16(As + row*AW + kc, Ag + (size_t)(m0+row)*K + kt*32 + kc);
        }
        #pragma unroll
        for (int i = 0; i < 2; i++) {
            int c = tid + i*512;
            int row = c >> 2, kc = (c & 3) * 8;
            cp16(Bs + row*AW + kc, Bg + (size_t)(n0+row)*K + kt*32 + kc);
        }
        cp_commit();
    };

    load_stage(0, 0);
    load_stage(1, 1);

    for (int it = 0; it < T; it++) {
        asm volatile("cp.async.wait_group 1;");
        __syncthreads();
        if (it + 2 < T) load_stage((it+2) % 3, it+2);
        else cp_commit();

        unsigned abase = sbase + (it % 3) * STG_B;
        unsigned bbase = abase + 128*AW*2;

        #pragma unroll
        for (int kk = 0; kk < 32; kk += 16) {
            unsigned a[4][4], b[4][2];
            #pragma unroll
            for (int mf = 0; mf < 4; mf++) {
                int row  = wm*64 + mf*16 + (lq & 1)*8 + lr;
                int kcol = kk + (lq >> 1)*8;
                ldm_x4(a[mf][0], a[mf][1], a[mf][2], a[mf][3],
                       abase + (row*AW + kcol)*2);
            }
            #pragma unroll
            for (int np = 0; np < 2; np++) {
                int row  = wn*32 + np*16 + (lq >> 1)*8 + lr;
                int kcol = kk + (lq & 1)*8;
                ldm_x4(b[np*2][0], b[np*2][1], b[np*2+1][0], b[np*2+1][1],
                       bbase + (row*AW + kcol)*2);
            }
            #pragma unroll
            for (int mf = 0; mf < 4; mf++)
                #pragma unroll
                for (int nf = 0; nf < 4; nf++)
                    mma_h(acc[mf][nf], a[mf], b[nf]);
        }
    }

    if (mode == 0) {
        #pragma unroll
        for (int mf = 0; mf < 4; mf++)
            #pragma unroll
            for (int nf = 0; nf < 4; nf++) {
                int row = m0 + wm*64 + mf*16 + g;
                int col = n0 + wn*32 + nf*8 + 2*t4;
                *(float2*)(C + (size_t)row*N + col) =
                    make_float2(acc[mf][nf][0], acc[mf][nf][1]);
                *(float2*)(C + (size_t)(row+8)*N + col) =
                    make_float2(acc[mf][nf][2], acc[mf][nf][3]);
            }
    } else {
        #pragma unroll
        for (int nf = 0; nf < 4; nf++) {
            int n   = n0 + wn*32 + nf*8 + 2*t4;
            int t   = n / 2048;
            int rem = n % 2048;
            int h   = rem >> 7;
            int d   = rem & 127;
            int j   = d >> 1;
            __half* dst = (t == 0) ? g_Q : (t == 1) ? g_K : g_V;
            #pragma unroll
            for (int mf = 0; mf < 4; mf++) {
                #pragma unroll
                for (int half = 0; half < 2; half++) {
                    int row = m0 + wm*64 + mf*16 + g + half*8;
                    int b = row >> 11, s = row & 2047;
                    float c0 = acc[mf][nf][half*2];
                    float c1 = acc[mf][nf][half*2 + 1];
                    __half2* p = (__half2*)(dst
                        + (((size_t)(b*Hc + h)*Sc + s) << 7) + d);
                    if (t == 2) *p = __floats2half2_rn(c0, c1);
                    else {
                        float cs = g_cos[s*64 + j], sn = g_sin[s*64 + j];
                        *p = __floats2half2_rn(c0*cs - c1*sn, c0*sn + c1*cs);
                    }
                }
            }
        }
    }
}

// ---------------------------------------------------------------------------
// fp16 flash attention. BM=128, BN=64, 256 threads (8 warps x 16 q-rows).
// K double-buffered, V triple-buffered; combined {K,V} commit groups;
// wait_group 1 at iter top (no full pipeline drains).
// ---------------------------------------------------------------------------
#define QW 136
#define PW 72
#define KV_H (64*QW)                  // halves per K/V tile

__global__ __launch_bounds__(256, 1) void flash_h() {
    extern __shared__ __half sh[];
    __half* Qs = sh;                   // [128][136]
    __half* Ks = Qs + 128*QW;          // [2][64][136]
    __half* Vs = Ks + 2*KV_H;          // [3][64][136]
    __half* Ps = Vs + 3*KV_H;          // 8 x [16][72]

    int tid  = threadIdx.x;
    int warp = tid >> 5, lane = tid & 31;
    int lr = lane & 7, lq = lane >> 3;
    int g = lane >> 2, t4 = lane & 3;
    int qb = blockIdx.x, bh = blockIdx.y;

    const __half* Qg = g_Q + (((size_t)bh*Sc + qb*128) << 7);
    const __half* Kg = g_K + ((size_t)bh*Sc << 7);
    const __half* Vg = g_V + ((size_t)bh*Sc << 7);

    unsigned qbase = smem_u32(Qs);
    unsigned pbase = smem_u32(Ps) + warp*16*PW*2;

    auto load_k = [&](int kt) {
        __half* dst = Ks + (kt & 1) * KV_H;
        #pragma unroll
        for (int i = 0; i < 4; i++) {
            int c = tid + i*256;
            int row = c >> 4, kc = (c & 15) * 8;
            cp16(dst + row*QW + kc, Kg + (size_t)kt*8192 + row*128 + kc);
        }
    };
    auto load_v = [&](int kt) {
        __half* dst = Vs + (kt % 3) * KV_H;
        #pragma unroll
        for (int i = 0; i < 4; i++) {
            int c = tid + i*256;
            int row = c >> 4, kc = (c & 15) * 8;
            cp16(dst + row*QW + kc, Vg + (size_t)kt*8192 + row*128 + kc);
        }
    };

    // Prologue: G0 = {Q, K0, V0}, G1 = {K1, V1}
    #pragma unroll
    for (int i = 0; i < 8; i++) {
        int c = tid + i*256;
        int row = c >> 4, kc = (c & 15) * 8;
        cp16(Qs + row*QW + kc, Qg + row*128 + kc);
    }
    load_k(0); load_v(0); cp_commit();
    load_k(1); load_v(1); cp_commit();

    float m_i[2] = {-INFINITY, -INFINITY}, l_i[2] = {0.f, 0.f};
    float o[16][4];
    #pragma unroll
    for (int nf = 0; nf < 16; nf++)
        #pragma unroll
        for (int r = 0; r < 4; r++) o[nf][r] = 0.f;

    const float scale = 0.08838834764831845f;
    int rbase = warp * 16;

    const int NT = Sc/64;
    for (int kt = 0; kt < NT; kt++) {
        // retire G(kt)
        asm volatile("cp.async.wait_group 1;");
        __syncthreads();

        unsigned kbase = smem_u32(Ks + (kt & 1) * KV_H);
        unsigned vbase = smem_u32(Vs + (kt % 3) * KV_H);

        // S = Q @ K^T
        float s[8][4];
        #pragma unroll
        for (int nf = 0; nf < 8; nf++)
            #pragma unroll
            for (int r = 0; r < 4; r++) s[nf][r] = 0.f;

        #pragma unroll
        for (int ks = 0; ks < 8; ks++) {
            int kd = ks*16;
            unsigned a[4], b[8][2];
            {
                int row  = rbase + (lq & 1)*8 + lr;
                int kcol = kd + (lq >> 1)*8;
                ldm_x4(a[0], a[1], a[2], a[3], qbase + (row*QW + kcol)*2);
            }
            #pragma unroll
            for (int np = 0; np < 4; np++) {
                int row  = np*16 + (lq >> 1)*8 + lr;
                int kcol = kd + (lq & 1)*8;
                ldm_x4(b[np*2][0], b[np*2][1], b[np*2+1][0], b[np*2+1][1],
                       kbase + (row*QW + kcol)*2);
            }
            #pragma unroll
            for (int nf = 0; nf < 8; nf++) mma_h(s[nf], a, b[nf]);
        }

        // online softmax
        #pragma unroll
        for (int half = 0; half < 2; half++) {
            float mx = -INFINITY;
            #pragma unroll
            for (int nf = 0; nf < 8; nf++)
                mx = fmaxf(mx, fmaxf(s[nf][half*2], s[nf][half*2+1]));
            mx *= scale;
            mx = fmaxf(mx, __shfl_xor_sync(0xffffffffu, mx, 1));
            mx = fmaxf(mx, __shfl_xor_sync(0xffffffffu, mx, 2));
            float m_new = fmaxf(m_i[half], mx);
            float corr  = __expf(m_i[half] - m_new);
            float lsum  = 0.f;
            #pragma unroll
            for (int nf = 0; nf < 8; nf++) {
                float p0 = __expf(s[nf][half*2]   * scale - m_new);
                float p1 = __expf(s[nf][half*2+1] * scale - m_new);
                s[nf][half*2]   = p0;
                s[nf][half*2+1] = p1;
                lsum += p0 + p1;
            }
            lsum += __shfl_xor_sync(0xffffffffu, lsum, 1);
            lsum += __shfl_xor_sync(0xffffffffu, lsum, 2);
            l_i[half] = l_i[half] * corr + lsum;
            m_i[half] = m_new;
            #pragma unroll
            for (int nf = 0; nf < 16; nf++) {
                o[nf][half*2]   *= corr;
                o[nf][half*2+1] *= corr;
            }
        }

        // P -> smem (fp16, per-warp slab)
        __half* Pw = Ps + warp*16*PW;
        #pragma unroll
        for (int nf = 0; nf < 8; nf++) {
            int col = nf*8 + 2*t4;
            *(__half2*)&Pw[g*PW + col]     = __floats2half2_rn(s[nf][0], s[nf][1]);
            *(__half2*)&Pw[(g+8)*PW + col] = __floats2half2_rn(s[nf][2], s[nf][3]);
        }
        __syncwarp();

        // all warps done reading Ks[kt&1] -> safe to overwrite
        __syncthreads();
        if (kt + 2 < NT) { load_k(kt+2); load_v(kt+2); }
        cp_commit();      // G(kt+2)

        // O += P @ V
        #pragma unroll
        for (int ks = 0; ks < 4; ks++) {
            int kv = ks*16;
            unsigned a[4], b[16][2];
            {
                int row  = (lq & 1)*8 + lr;
                int kcol = kv + (lq >> 1)*8;
                ldm_x4(a[0], a[1], a[2], a[3], pbase + (row*PW + kcol)*2);
            }
            #pragma unroll
            for (int np = 0; np < 8; np++) {
                int row = kv + (lq & 1)*8 + lr;
                int col = np*16 + (lq >> 1)*8;
                ldm_x4_t(b[np*2][0], b[np*2][1], b[np*2+1][0], b[np*2+1][1],
                         vbase + (row*QW + col)*2);
            }
            #pragma unroll
            for (int nf = 0; nf < 16; nf++) mma_h(o[nf], a, b[nf]);
        }
    }

    // epilogue: normalize, write fp16 to g_attn [b, s, h*128+d]
    int b = bh / Hc, h = bh % Hc;
    float inv0 = 1.f / l_i[0], inv1 = 1.f / l_i[1];
    #pragma unroll
    for (int nf = 0; nf < 16; nf++) {
        int d = nf*8 + 2*t4;
        int r0 = qb*128 + rbase + g;
        __half2* p0 = (__half2*)(g_attn + (((size_t)(b*Sc + r0)) << 11) + h*128 + d);
        *p0 = __floats2half2_rn(o[nf][0]*inv0, o[nf][1]*inv0);
        __half2* p1 = (__half2*)(g_attn + (((size_t)(b*Sc + r0 + 8)) << 11) + h*128 + d);
        *p1 = __floats2half2_rn(o[nf][2]*inv1, o[nf][3]*inv1);
    }
}

// ---------------------------------------------------------------------------
extern "C" void kernel_launch(void* const* d_in, const int* in_sizes, int n_in,
                              void* d_out, int out_size) {
    const float *x = nullptr, *wqkv = nullptr, *wout = nullptr;
    for (int i = 0; i < n_in; i++) {
        int sz = in_sizes[i];
        if (sz == Bc*Sc*Ec)     x    = (const float*)d_in[i];
        else if (sz == Ec*3*Ac) wqkv = (const float*)d_in[i];
        else if (sz == Ac*Ec)   wout = (const float*)d_in[i];
    }
    float* out = (float*)d_out;
    const int M = Bc * Sc;  // 4096

    cudaFuncSetAttribute(gemm_h,
        cudaFuncAttributeMaxDynamicSharedMemorySize, 3*STG_B);
    size_t fsmem = (size_t)(128*QW + 2*KV_H + 3*KV_H + 8*16*PW) * sizeof(__half);
    cudaFuncSetAttribute(flash_h,
        cudaFuncAttributeMaxDynamicSharedMemorySize, (int)fsmem);

    rope_table_kernel<<<(Sc*(HDc/2) + 255)/256, 256>>>();

    __half *dxh, *dwq, *dwo;
    cudaGetSymbolAddress((void**)&dxh, g_x_h);
    cudaGetSymbolAddress((void**)&dwq, g_wqkv_t);
    cudaGetSymbolAddress((void**)&dwo, g_wout_t);

    {
        int n4 = Bc*Sc*Ec/4;
        cvt_h<<<(n4+255)/256, 256>>>((const float4*)x, (__half2*)dxh, n4);
    }
    transpose_cvt_h<<<dim3(3*Ac/32, Ec/32), 256>>>(wqkv, dwq, Ec, 3*Ac);
    transpose_cvt_h<<<dim3(Ec/32,   Ac/32), 256>>>(wout, dwo, Ac, Ec);

    // QKV GEMM + RoPE scatter  (CTA 128x256, 512 threads)
    gemm_h<<<dim3(3*Ac/256, M/128), 512, 3*STG_B>>>(nullptr, 3*Ac, Ec, 1);

    // Flash attention
    flash_h<<<dim3(Sc/128, Bc*Hc), 256, fsmem>>>();

    // Output projection
    gemm_h<<<dim3(Ec/256, M/128), 512, 3*STG_B>>>(out, Ec, Ac, 0);
}

// round 12
// speedup vs baseline: 1.1252x; 1.1252x over previous
#include <cuda_runtime.h>
#include <cuda_fp16.h>
#include <math.h>
#include <stdint.h>

#define Bc  2
#define Sc  2048
#define Ec  2048
#define Ac  2048
#define Hc  16
#define HDc 128

// Scratch (device globals), fp16 operands.
__device__ __half g_Q[Bc*Hc*Sc*HDc];
__device__ __half g_K[Bc*Hc*Sc*HDc];
__device__ __half g_V[Bc*Hc*Sc*HDc];
__device__ __half g_attn[Bc*Sc*Ac];          // attention out (fp16)
__device__ __half g_x_h[Bc*Sc*Ec];           // x fp16 [4096][2048]
__device__ __half g_wqkv_t[3*Ac*Ec];         // W_qkv^T fp16 [6144][2048]
__device__ __half g_wout_t[Ec*Ac];           // W_out^T fp16 [2048][2048]
__device__ float  g_cos[Sc*(HDc/2)];
__device__ float  g_sin[Sc*(HDc/2)];

// ---------------------------------------------------------------------------
__device__ __forceinline__ void mma_h(float* c, const unsigned* a, const unsigned* b) {
    asm volatile("mma.sync.aligned.m16n8k16.row.col.f32.f16.f16.f32 "
        "{%0,%1,%2,%3}, {%4,%5,%6,%7}, {%8,%9}, {%0,%1,%2,%3};"
        : "+f"(c[0]), "+f"(c[1]), "+f"(c[2]), "+f"(c[3])
        : "r"(a[0]), "r"(a[1]), "r"(a[2]), "r"(a[3]), "r"(b[0]), "r"(b[1]));
}
__device__ __forceinline__ void ldm_x4(unsigned& r0, unsigned& r1, unsigned& r2,
                                       unsigned& r3, unsigned addr) {
    asm volatile("ldmatrix.sync.aligned.m8n8.x4.shared.b16 {%0,%1,%2,%3}, [%4];"
        : "=r"(r0), "=r"(r1), "=r"(r2), "=r"(r3) : "r"(addr));
}
__device__ __forceinline__ void ldm_x4_t(unsigned& r0, unsigned& r1, unsigned& r2,
                                         unsigned& r3, unsigned addr) {
    asm volatile("ldmatrix.sync.aligned.m8n8.x4.trans.shared.b16 {%0,%1,%2,%3}, [%4];"
        : "=r"(r0), "=r"(r1), "=r"(r2), "=r"(r3) : "r"(addr));
}
__device__ __forceinline__ void cp16(void* smem_dst, const void* gsrc) {
    unsigned d = (unsigned)__cvta_generic_to_shared(smem_dst);
    asm volatile("cp.async.cg.shared.global [%0], [%1], 16;" :: "r"(d), "l"(gsrc));
}
__device__ __forceinline__ void cp_commit() { asm volatile("cp.async.commit_group;"); }
__device__ __forceinline__ unsigned smem_u32(const void* p) {
    return (unsigned)__cvta_generic_to_shared(p);
}

// ---------------------------------------------------------------------------
__global__ void rope_table_kernel() {
    int idx = blockIdx.x * blockDim.x + threadIdx.x;
    if (idx >= Sc * (HDc/2)) return;
    int pos = idx / (HDc/2);
    int j   = idx % (HDc/2);
    double inv = pow(10000.0, -((double)(2*j)) / (double)HDc);
    double a = (double)pos * inv;
    g_cos[idx] = (float)cos(a);
    g_sin[idx] = (float)sin(a);
}

__global__ void cvt_h(const float4* __restrict__ src, __half2* __restrict__ dst, int n4) {
    int i = blockIdx.x * blockDim.x + threadIdx.x;
    if (i < n4) {
        float4 v = src[i];
        dst[2*i]   = __floats2half2_rn(v.x, v.y);
        dst[2*i+1] = __floats2half2_rn(v.z, v.w);
    }
}

__global__ __launch_bounds__(256) void transpose_cvt_h(
    const float* __restrict__ src, __half* __restrict__ dst, int R, int Ccols) {
    __shared__ __half tile[32][33];
    int c0 = blockIdx.x*32, r0 = blockIdx.y*32;
    int tx = threadIdx.x & 31, ty = threadIdx.x >> 5;
    #pragma unroll
    for (int i = 0; i < 4; i++)
        tile[ty + 8*i][tx] = __float2half(src[(size_t)(r0 + ty + 8*i)*Ccols + c0 + tx]);
    __syncthreads();
    #pragma unroll
    for (int i = 0; i < 4; i++)
        dst[(size_t)(c0 + ty + 8*i)*R + r0 + tx] = tile[tx][ty + 8*i];
}

// ---------------------------------------------------------------------------
// fp16 GEMM: CTA 128x128, BK=32, 8 warps (2x4), warp tile 64x32, 4-stage
// cp.async pipeline, ldmatrix fragments. K-major operands. 2 CTAs/SM.
// mode 1: A=g_x_h, B=g_wqkv_t -> RoPE scatter to g_Q/g_K/g_V.
// mode 0: A=g_attn, B=g_wout_t -> fp32 C.
// ---------------------------------------------------------------------------
#define AW 40                         // padded row width (halves)
#define NSTG 4
#define STG_H (2*128*AW)              // halves per stage (A+B)
#define STG_B (STG_H*2)               // bytes per stage (20480)

__global__ __launch_bounds__(256, 2) void gemm_h(
    float* __restrict__ C, int N, int K, int mode)
{
    extern __shared__ __half hs[];

    const __half* Ag = mode ? g_x_h : g_attn;
    const __half* Bg = mode ? g_wqkv_t : g_wout_t;

    int tid  = threadIdx.x;
    int warp = tid >> 5, lane = tid & 31;
    int lr = lane & 7, lq = lane >> 3;
    int g = lane >> 2, t4 = lane & 3;
    int wm = warp >> 2, wn = warp & 3;
    int m0 = blockIdx.y * 128, n0 = blockIdx.x * 128;
    unsigned sbase = smem_u32(hs);

    float acc[4][4][4];
    #pragma unroll
    for (int i = 0; i < 4; i++)
        #pragma unroll
        for (int j = 0; j < 4; j++)
            #pragma unroll
            for (int r = 0; r < 4; r++) acc[i][j][r] = 0.f;

    int T = K / 32;

    // stage loader: A tile 128x32, B tile 128x32 (both K-major)
    auto load_stage = [&](int s, int kt) {
        __half* As = hs + s*STG_H;
        __half* Bs = As + 128*AW;
        #pragma unroll
        for (int i = 0; i < 2; i++) {
            int c = tid + i*256;
            int row = c >> 2, kc = (c & 3) * 8;
            cp16(As + row*AW + kc, Ag + (size_t)(m0+row)*K + kt*32 + kc);
            cp16(Bs + row*AW + kc, Bg + (size_t)(n0+row)*K + kt*32 + kc);
        }
        cp_commit();
    };

    load_stage(0, 0);
    load_stage(1, 1);
    load_stage(2, 2);

    for (int it = 0; it < T; it++) {
        asm volatile("cp.async.wait_group 2;");
        __syncthreads();
        if (it + 3 < T) load_stage((it+3) % NSTG, it+3);
        else cp_commit();

        unsigned abase = sbase + (it % NSTG) * STG_B;
        unsigned bbase = abase + 128*AW*2;

        #pragma unroll
        for (int kk = 0; kk < 32; kk += 16) {
            unsigned a[4][4], b[4][2];
            #pragma unroll
            for (int mf = 0; mf < 4; mf++) {
                int row  = wm*64 + mf*16 + (lq & 1)*8 + lr;
                int kcol = kk + (lq >> 1)*8;
                ldm_x4(a[mf][0], a[mf][1], a[mf][2], a[mf][3],
                       abase + (row*AW + kcol)*2);
            }
            #pragma unroll
            for (int np = 0; np < 2; np++) {
                int row  = wn*32 + np*16 + (lq >> 1)*8 + lr;
                int kcol = kk + (lq & 1)*8;
                ldm_x4(b[np*2][0], b[np*2][1], b[np*2+1][0], b[np*2+1][1],
                       bbase + (row*AW + kcol)*2);
            }
            #pragma unroll
            for (int mf = 0; mf < 4; mf++)
                #pragma unroll
                for (int nf = 0; nf < 4; nf++)
                    mma_h(acc[mf][nf], a[mf], b[nf]);
        }
    }

    if (mode == 0) {
        #pragma unroll
        for (int mf = 0; mf < 4; mf++)
            #pragma unroll
            for (int nf = 0; nf < 4; nf++) {
                int row = m0 + wm*64 + mf*16 + g;
                int col = n0 + wn*32 + nf*8 + 2*t4;
                *(float2*)(C + (size_t)row*N + col) =
                    make_float2(acc[mf][nf][0], acc[mf][nf][1]);
                *(float2*)(C + (size_t)(row+8)*N + col) =
                    make_float2(acc[mf][nf][2], acc[mf][nf][3]);
            }
    } else {
        #pragma unroll
        for (int nf = 0; nf < 4; nf++) {
            int n   = n0 + wn*32 + nf*8 + 2*t4;
            int t   = n / 2048;
            int rem = n % 2048;
            int h   = rem >> 7;
            int d   = rem & 127;
            int j   = d >> 1;
            __half* dst = (t == 0) ? g_Q : (t == 1) ? g_K : g_V;
            #pragma unroll
            for (int mf = 0; mf < 4; mf++) {
                #pragma unroll
                for (int half = 0; half < 2; half++) {
                    int row = m0 + wm*64 + mf*16 + g + half*8;
                    int b = row >> 11, s = row & 2047;
                    float c0 = acc[mf][nf][half*2];
                    float c1 = acc[mf][nf][half*2 + 1];
                    __half2* p = (__half2*)(dst
                        + (((size_t)(b*Hc + h)*Sc + s) << 7) + d);
                    if (t == 2) *p = __floats2half2_rn(c0, c1);
                    else {
                        float cs = g_cos[s*64 + j], sn = g_sin[s*64 + j];
                        *p = __floats2half2_rn(c0*cs - c1*sn, c0*sn + c1*cs);
                    }
                }
            }
        }
    }
}

// ---------------------------------------------------------------------------
// fp16 flash attention (exact R7 802us version). BM=128, BN=64, 256 threads.
// V(kt) prefetch under S-compute, K(kt+1) prefetch under O-compute.
// ---------------------------------------------------------------------------
#define QW 136
#define PW 72

__global__ __launch_bounds__(256, 1) void flash_h() {
    extern __shared__ __half sh[];
    __half* Qs = sh;                   // [128][136]
    __half* Ks = Qs + 128*QW;          // [64][136]
    __half* Vs = Ks + 64*QW;           // [64][136]
    __half* Ps = Vs + 64*QW;           // 8 x [16][72]

    int tid  = threadIdx.x;
    int warp = tid >> 5, lane = tid & 31;
    int lr = lane & 7, lq = lane >> 3;
    int g = lane >> 2, t4 = lane & 3;
    int qb = blockIdx.x, bh = blockIdx.y;

    const __half* Qg = g_Q + (((size_t)bh*Sc + qb*128) << 7);
    const __half* Kg = g_K + ((size_t)bh*Sc << 7);
    const __half* Vg = g_V + ((size_t)bh*Sc << 7);

    unsigned qbase = smem_u32(Qs);
    unsigned kbase = smem_u32(Ks);
    unsigned vbase = smem_u32(Vs);
    unsigned pbase = smem_u32(Ps) + warp*16*PW*2;

    #pragma unroll
    for (int i = 0; i < 8; i++) {
        int c = tid + i*256;
        int row = c >> 4, kc = (c & 15) * 8;
        cp16(Qs + row*QW + kc, Qg + row*128 + kc);
    }
    #pragma unroll
    for (int i = 0; i < 4; i++) {
        int c = tid + i*256;
        int row = c >> 4, kc = (c & 15) * 8;
        cp16(Ks + row*QW + kc, Kg + row*128 + kc);
    }
    cp_commit();

    float m_i[2] = {-INFINITY, -INFINITY}, l_i[2] = {0.f, 0.f};
    float o[16][4];
    #pragma unroll
    for (int nf = 0; nf < 16; nf++)
        #pragma unroll
        for (int r = 0; r < 4; r++) o[nf][r] = 0.f;

    const float scale = 0.08838834764831845f;
    int rbase = warp * 16;

    asm volatile("cp.async.wait_group 0;");
    __syncthreads();

    for (int kt = 0; kt < Sc/64; kt++) {
        // prefetch V(kt) under S-compute
        #pragma unroll
        for (int i = 0; i < 4; i++) {
            int c = tid + i*256;
            int row = c >> 4, kc = (c & 15) * 8;
            cp16(Vs + row*QW + kc, Vg + (size_t)kt*8192 + row*128 + kc);
        }
        cp_commit();

        // S = Q @ K^T
        float s[8][4];
        #pragma unroll
        for (int nf = 0; nf < 8; nf++)
            #pragma unroll
            for (int r = 0; r < 4; r++) s[nf][r] = 0.f;

        #pragma unroll
        for (int ks = 0; ks < 8; ks++) {
            int kd = ks*16;
            unsigned a[4], b[8][2];
            {
                int row  = rbase + (lq & 1)*8 + lr;
                int kcol = kd + (lq >> 1)*8;
                ldm_x4(a[0], a[1], a[2], a[3], qbase + (row*QW + kcol)*2);
            }
            #pragma unroll
            for (int np = 0; np < 4; np++) {
                int row  = np*16 + (lq >> 1)*8 + lr;
                int kcol = kd + (lq & 1)*8;
                ldm_x4(b[np*2][0], b[np*2][1], b[np*2+1][0], b[np*2+1][1],
                       kbase + (row*QW + kcol)*2);
            }
            #pragma unroll
            for (int nf = 0; nf < 8; nf++) mma_h(s[nf], a, b[nf]);
        }

        // online softmax
        #pragma unroll
        for (int half = 0; half < 2; half++) {
            float mx = -INFINITY;
            #pragma unroll
            for (int nf = 0; nf < 8; nf++)
                mx = fmaxf(mx, fmaxf(s[nf][half*2], s[nf][half*2+1]));
            mx *= scale;
            mx = fmaxf(mx, __shfl_xor_sync(0xffffffffu, mx, 1));
            mx = fmaxf(mx, __shfl_xor_sync(0xffffffffu, mx, 2));
            float m_new = fmaxf(m_i[half], mx);
            float corr  = __expf(m_i[half] - m_new);
            float lsum  = 0.f;
            #pragma unroll
            for (int nf = 0; nf < 8; nf++) {
                float p0 = __expf(s[nf][half*2]   * scale - m_new);
                float p1 = __expf(s[nf][half*2+1] * scale - m_new);
                s[nf][half*2]   = p0;
                s[nf][half*2+1] = p1;
                lsum += p0 + p1;
            }
            lsum += __shfl_xor_sync(0xffffffffu, lsum, 1);
            lsum += __shfl_xor_sync(0xffffffffu, lsum, 2);
            l_i[half] = l_i[half] * corr + lsum;
            m_i[half] = m_new;
            #pragma unroll
            for (int nf = 0; nf < 16; nf++) {
                o[nf][half*2]   *= corr;
                o[nf][half*2+1] *= corr;
            }
        }

        // P -> smem (fp16)
        __half* Pw = Ps + warp*16*PW;
        #pragma unroll
        for (int nf = 0; nf < 8; nf++) {
            int col = nf*8 + 2*t4;
            *(__half2*)&Pw[g*PW + col]     = __floats2half2_rn(s[nf][0], s[nf][1]);
            *(__half2*)&Pw[(g+8)*PW + col] = __floats2half2_rn(s[nf][2], s[nf][3]);
        }

        asm volatile("cp.async.wait_group 0;");   // V(kt) landed
        __syncthreads();

        // prefetch K(kt+1) under O-compute
        if (kt + 1 < Sc/64) {
            #pragma unroll
            for (int i = 0; i < 4; i++) {
                int c = tid + i*256;
                int row = c >> 4, kc = (c & 15) * 8;
                cp16(Ks + row*QW + kc, Kg + (size_t)(kt+1)*8192 + row*128 + kc);
            }
        }
        cp_commit();

        // O += P @ V
        #pragma unroll
        for (int ks = 0; ks < 4; ks++) {
            int kv = ks*16;
            unsigned a[4], b[16][2];
            {
                int row  = (lq & 1)*8 + lr;
                int kcol = kv + (lq >> 1)*8;
                ldm_x4(a[0], a[1], a[2], a[3], pbase + (row*PW + kcol)*2);
            }
            #pragma unroll
            for (int np = 0; np < 8; np++) {
                int row = kv + (lq & 1)*8 + lr;
                int col = np*16 + (lq >> 1)*8;
                ldm_x4_t(b[np*2][0], b[np*2][1], b[np*2+1][0], b[np*2+1][1],
                         vbase + (row*QW + col)*2);
            }
            #pragma unroll
            for (int nf = 0; nf < 16; nf++) mma_h(o[nf], a, b[nf]);
        }

        asm volatile("cp.async.wait_group 0;");   // K(kt+1) landed
        __syncthreads();
    }

    // epilogue: normalize, write fp16 to g_attn [b, s, h*128+d]
    int b = bh / Hc, h = bh % Hc;
    float inv0 = 1.f / l_i[0], inv1 = 1.f / l_i[1];
    #pragma unroll
    for (int nf = 0; nf < 16; nf++) {
        int d = nf*8 + 2*t4;
        int r0 = qb*128 + rbase + g;
        __half2* p0 = (__half2*)(g_attn + (((size_t)(b*Sc + r0)) << 11) + h*128 + d);
        *p0 = __floats2half2_rn(o[nf][0]*inv0, o[nf][1]*inv0);
        __half2* p1 = (__half2*)(g_attn + (((size_t)(b*Sc + r0 + 8)) << 11) + h*128 + d);
        *p1 = __floats2half2_rn(o[nf][2]*inv1, o[nf][3]*inv1);
    }
}

// ---------------------------------------------------------------------------
extern "C" void kernel_launch(void* const* d_in, const int* in_sizes, int n_in,
                              void* d_out, int out_size) {
    const float *x = nullptr, *wqkv = nullptr, *wout = nullptr;
    for (int i = 0; i < n_in; i++) {
        int sz = in_sizes[i];
        if (sz == Bc*Sc*Ec)     x    = (const float*)d_in[i];
        else if (sz == Ec*3*Ac) wqkv = (const float*)d_in[i];
        else if (sz == Ac*Ec)   wout = (const float*)d_in[i];
    }
    float* out = (float*)d_out;
    const int M = Bc * Sc;  // 4096

    cudaFuncSetAttribute(gemm_h,
        cudaFuncAttributeMaxDynamicSharedMemorySize, NSTG*STG_B);
    size_t fsmem = (size_t)(128*QW + 64*QW + 64*QW + 8*16*PW) * sizeof(__half);
    cudaFuncSetAttribute(flash_h,
        cudaFuncAttributeMaxDynamicSharedMemorySize, (int)fsmem);

    rope_table_kernel<<<(Sc*(HDc/2) + 255)/256, 256>>>();

    __half *dxh, *dwq, *dwo;
    cudaGetSymbolAddress((void**)&dxh, g_x_h);
    cudaGetSymbolAddress((void**)&dwq, g_wqkv_t);
    cudaGetSymbolAddress((void**)&dwo, g_wout_t);

    {
        int n4 = Bc*Sc*Ec/4;
        cvt_h<<<(n4+255)/256, 256>>>((const float4*)x, (__half2*)dxh, n4);
    }
    transpose_cvt_h<<<dim3(3*Ac/32, Ec/32), 256>>>(wqkv, dwq, Ec, 3*Ac);
    transpose_cvt_h<<<dim3(Ec/32,   Ac/32), 256>>>(wout, dwo, Ac, Ec);

    // QKV GEMM + RoPE scatter
    gemm_h<<<dim3(3*Ac/128, M/128), 256, NSTG*STG_B>>>(nullptr, 3*Ac, Ec, 1);

    // Flash attention
    flash_h<<<dim3(Sc/128, Bc*Hc), 256, fsmem>>>();

    // Output projection
    gemm_h<<<dim3(Ec/128, M/128), 256, NSTG*STG_B>>>(out, Ec, Ac, 0);
}

// round 15
// speedup vs baseline: 1.1765x; 1.0456x over previous
#include <cuda_runtime.h>
#include <cuda_fp16.h>
#include <math.h>
#include <stdint.h>

#define Bc  2
#define Sc  2048
#define Ec  2048
#define Ac  2048
#define Hc  16
#define HDc 128

// Scratch (device globals), fp16 operands.
__device__ __half g_Q[Bc*Hc*Sc*HDc];
__device__ __half g_K[Bc*Hc*Sc*HDc];
__device__ __half g_V[Bc*Hc*Sc*HDc];
__device__ __half g_attn[Bc*Sc*Ac];          // attention out (fp16)
__device__ __half g_x_h[Bc*Sc*Ec];           // x fp16 [4096][2048]
__device__ __half g_wqkv_t[3*Ac*Ec];         // W_qkv^T fp16 [6144][2048]
__device__ __half g_wout_t[Ec*Ac];           // W_out^T fp16 [2048][2048]
__device__ float  g_cos[Sc*(HDc/2)];
__device__ float  g_sin[Sc*(HDc/2)];

// ---------------------------------------------------------------------------
__device__ __forceinline__ void mma_h(float* c, const unsigned* a, const unsigned* b) {
    asm volatile("mma.sync.aligned.m16n8k16.row.col.f32.f16.f16.f32 "
        "{%0,%1,%2,%3}, {%4,%5,%6,%7}, {%8,%9}, {%0,%1,%2,%3};"
        : "+f"(c[0]), "+f"(c[1]), "+f"(c[2]), "+f"(c[3])
        : "r"(a[0]), "r"(a[1]), "r"(a[2]), "r"(a[3]), "r"(b[0]), "r"(b[1]));
}
__device__ __forceinline__ void ldm_x4(unsigned& r0, unsigned& r1, unsigned& r2,
                                       unsigned& r3, unsigned addr) {
    asm volatile("ldmatrix.sync.aligned.m8n8.x4.shared.b16 {%0,%1,%2,%3}, [%4];"
        : "=r"(r0), "=r"(r1), "=r"(r2), "=r"(r3) : "r"(addr));
}
__device__ __forceinline__ void ldm_x4_t(unsigned& r0, unsigned& r1, unsigned& r2,
                                         unsigned& r3, unsigned addr) {
    asm volatile("ldmatrix.sync.aligned.m8n8.x4.trans.shared.b16 {%0,%1,%2,%3}, [%4];"
        : "=r"(r0), "=r"(r1), "=r"(r2), "=r"(r3) : "r"(addr));
}
__device__ __forceinline__ void cp16(void* smem_dst, const void* gsrc) {
    unsigned d = (unsigned)__cvta_generic_to_shared(smem_dst);
    asm volatile("cp.async.cg.shared.global [%0], [%1], 16;" :: "r"(d), "l"(gsrc));
}
__device__ __forceinline__ void cp_commit() { asm volatile("cp.async.commit_group;"); }
__device__ __forceinline__ unsigned smem_u32(const void* p) {
    return (unsigned)__cvta_generic_to_shared(p);
}

// ---------------------------------------------------------------------------
__global__ void rope_table_kernel() {
    int idx = blockIdx.x * blockDim.x + threadIdx.x;
    if (idx >= Sc * (HDc/2)) return;
    int pos = idx / (HDc/2);
    int j   = idx % (HDc/2);
    double inv = pow(10000.0, -((double)(2*j)) / (double)HDc);
    double a = (double)pos * inv;
    g_cos[idx] = (float)cos(a);
    g_sin[idx] = (float)sin(a);
}

__global__ void cvt_h(const float4* __restrict__ src, __half2* __restrict__ dst, int n4) {
    int i = blockIdx.x * blockDim.x + threadIdx.x;
    if (i < n4) {
        float4 v = src[i];
        dst[2*i]   = __floats2half2_rn(v.x, v.y);
        dst[2*i+1] = __floats2half2_rn(v.z, v.w);
    }
}

__global__ __launch_bounds__(256) void transpose_cvt_h(
    const float* __restrict__ src, __half* __restrict__ dst, int R, int Ccols) {
    __shared__ __half tile[32][33];
    int c0 = blockIdx.x*32, r0 = blockIdx.y*32;
    int tx = threadIdx.x & 31, ty = threadIdx.x >> 5;
    #pragma unroll
    for (int i = 0; i < 4; i++)
        tile[ty + 8*i][tx] = __float2half(src[(size_t)(r0 + ty + 8*i)*Ccols + c0 + tx]);
    __syncthreads();
    #pragma unroll
    for (int i = 0; i < 4; i++)
        dst[(size_t)(c0 + ty + 8*i)*R + r0 + tx] = tile[tx][ty + 8*i];
}

// ---------------------------------------------------------------------------
// fp16 GEMM: CTA 128x128, BK=32, 4 warps (2x2 grid), warp tile 64x64,
// 3-stage cp.async, ldmatrix. 128 threads, 2 CTAs/SM.
// Halved LDSM traffic per FLOP vs the 64x32 warp tile (smem-BW bound lifted).
// mode 1: A=g_x_h, B=g_wqkv_t -> RoPE scatter to g_Q/g_K/g_V.
// mode 0: A=g_attn, B=g_wout_t -> fp32 C.
// ---------------------------------------------------------------------------
#define AW 40                         // padded row width (halves)
#define STG_H (2*128*AW)              // halves per stage (A+B)
#define STG_B (STG_H*2)               // bytes per stage (20480)

__global__ __launch_bounds__(128, 2) void gemm_h(
    float* __restrict__ C, int N, int K, int mode)
{
    extern __shared__ __half hs[];

    const __half* Ag = mode ? g_x_h : g_attn;
    const __half* Bg = mode ? g_wqkv_t : g_wout_t;

    int tid  = threadIdx.x;
    int warp = tid >> 5, lane = tid & 31;
    int lr = lane & 7, lq = lane >> 3;
    int g = lane >> 2, t4 = lane & 3;
    int wm = warp >> 1, wn = warp & 1;          // 2x2 warp grid, 64x64 tiles
    int m0 = blockIdx.y * 128, n0 = blockIdx.x * 128;
    unsigned sbase = smem_u32(hs);

    float acc[4][8][4];
    #pragma unroll
    for (int i = 0; i < 4; i++)
        #pragma unroll
        for (int j = 0; j < 8; j++)
            #pragma unroll
            for (int r = 0; r < 4; r++) acc[i][j][r] = 0.f;

    int T = K / 32;

    // stage loader: A 128x32 (512 chunks) + B 128x32 (512 chunks), 128 thr
    auto load_stage = [&](int s, int kt) {
        __half* As = hs + s*STG_H;
        __half* Bs = As + 128*AW;
        #pragma unroll
        for (int i = 0; i < 4; i++) {
            int c = tid + i*128;
            int row = c >> 2, kc = (c & 3) * 8;
            cp16(As + row*AW + kc, Ag + (size_t)(m0+row)*K + kt*32 + kc);
            cp16(Bs + row*AW + kc, Bg + (size_t)(n0+row)*K + kt*32 + kc);
        }
        cp_commit();
    };

    load_stage(0, 0);
    load_stage(1, 1);

    for (int it = 0; it < T; it++) {
        asm volatile("cp.async.wait_group 1;");
        __syncthreads();
        if (it + 2 < T) load_stage((it+2) % 3, it+2);
        else cp_commit();

        unsigned abase = sbase + (it % 3) * STG_B;
        unsigned bbase = abase + 128*AW*2;

        #pragma unroll
        for (int kk = 0; kk < 32; kk += 16) {
            unsigned a[4][4], b[8][2];
            #pragma unroll
            for (int mf = 0; mf < 4; mf++) {
                int row  = wm*64 + mf*16 + (lq & 1)*8 + lr;
                int kcol = kk + (lq >> 1)*8;
                ldm_x4(a[mf][0], a[mf][1], a[mf][2], a[mf][3],
                       abase + (row*AW + kcol)*2);
            }
            #pragma unroll
            for (int np = 0; np < 4; np++) {
                int row  = wn*64 + np*16 + (lq >> 1)*8 + lr;
                int kcol = kk + (lq & 1)*8;
                ldm_x4(b[np*2][0], b[np*2][1], b[np*2+1][0], b[np*2+1][1],
                       bbase + (row*AW + kcol)*2);
            }
            #pragma unroll
            for (int mf = 0; mf < 4; mf++)
                #pragma unroll
                for (int nf = 0; nf < 8; nf++)
                    mma_h(acc[mf][nf], a[mf], b[nf]);
        }
    }

    if (mode == 0) {
        #pragma unroll
        for (int mf = 0; mf < 4; mf++)
            #pragma unroll
            for (int nf = 0; nf < 8; nf++) {
                int row = m0 + wm*64 + mf*16 + g;
                int col = n0 + wn*64 + nf*8 + 2*t4;
                *(float2*)(C + (size_t)row*N + col) =
                    make_float2(acc[mf][nf][0], acc[mf][nf][1]);
                *(float2*)(C + (size_t)(row+8)*N + col) =
                    make_float2(acc[mf][nf][2], acc[mf][nf][3]);
            }
    } else {
        #pragma unroll
        for (int nf = 0; nf < 8; nf++) {
            int n   = n0 + wn*64 + nf*8 + 2*t4;
            int t   = n / 2048;
            int rem = n % 2048;
            int h   = rem >> 7;
            int d   = rem & 127;
            int j   = d >> 1;
            __half* dst = (t == 0) ? g_Q : (t == 1) ? g_K : g_V;
            #pragma unroll
            for (int mf = 0; mf < 4; mf++) {
                #pragma unroll
                for (int half = 0; half < 2; half++) {
                    int row = m0 + wm*64 + mf*16 + g + half*8;
                    int b = row >> 11, s = row & 2047;
                    float c0 = acc[mf][nf][half*2];
                    float c1 = acc[mf][nf][half*2 + 1];
                    __half2* p = (__half2*)(dst
                        + (((size_t)(b*Hc + h)*Sc + s) << 7) + d);
                    if (t == 2) *p = __floats2half2_rn(c0, c1);
                    else {
                        float cs = g_cos[s*64 + j], sn = g_sin[s*64 + j];
                        *p = __floats2half2_rn(c0*cs - c1*sn, c0*sn + c1*cs);
                    }
                }
            }
        }
    }
}

// ---------------------------------------------------------------------------
// fp16 flash attention (exact R7 802us version). BM=128, BN=64, 256 threads.
// V(kt) prefetch under S-compute, K(kt+1) prefetch under O-compute.
// ---------------------------------------------------------------------------
#define QW 136
#define PW 72

__global__ __launch_bounds__(256, 1) void flash_h() {
    extern __shared__ __half sh[];
    __half* Qs = sh;                   // [128][136]
    __half* Ks = Qs + 128*QW;          // [64][136]
    __half* Vs = Ks + 64*QW;           // [64][136]
    __half* Ps = Vs + 64*QW;           // 8 x [16][72]

    int tid  = threadIdx.x;
    int warp = tid >> 5, lane = tid & 31;
    int lr = lane & 7, lq = lane >> 3;
    int g = lane >> 2, t4 = lane & 3;
    int qb = blockIdx.x, bh = blockIdx.y;

    const __half* Qg = g_Q + (((size_t)bh*Sc + qb*128) << 7);
    const __half* Kg = g_K + ((size_t)bh*Sc << 7);
    const __half* Vg = g_V + ((size_t)bh*Sc << 7);

    unsigned qbase = smem_u32(Qs);
    unsigned kbase = smem_u32(Ks);
    unsigned vbase = smem_u32(Vs);
    unsigned pbase = smem_u32(Ps) + warp*16*PW*2;

    #pragma unroll
    for (int i = 0; i < 8; i++) {
        int c = tid + i*256;
        int row = c >> 4, kc = (c & 15) * 8;
        cp16(Qs + row*QW + kc, Qg + row*128 + kc);
    }
    #pragma unroll
    for (int i = 0; i < 4; i++) {
        int c = tid + i*256;
        int row = c >> 4, kc = (c & 15) * 8;
        cp16(Ks + row*QW + kc, Kg + row*128 + kc);
    }
    cp_commit();

    float m_i[2] = {-INFINITY, -INFINITY}, l_i[2] = {0.f, 0.f};
    float o[16][4];
    #pragma unroll
    for (int nf = 0; nf < 16; nf++)
        #pragma unroll
        for (int r = 0; r < 4; r++) o[nf][r] = 0.f;

    const float scale = 0.08838834764831845f;
    int rbase = warp * 16;

    asm volatile("cp.async.wait_group 0;");
    __syncthreads();

    for (int kt = 0; kt < Sc/64; kt++) {
        // prefetch V(kt) under S-compute
        #pragma unroll
        for (int i = 0; i < 4; i++) {
            int c = tid + i*256;
            int row = c >> 4, kc = (c & 15) * 8;
            cp16(Vs + row*QW + kc, Vg + (size_t)kt*8192 + row*128 + kc);
        }
        cp_commit();

        // S = Q @ K^T
        float s[8][4];
        #pragma unroll
        for (int nf = 0; nf < 8; nf++)
            #pragma unroll
            for (int r = 0; r < 4; r++) s[nf][r] = 0.f;

        #pragma unroll
        for (int ks = 0; ks < 8; ks++) {
            int kd = ks*16;
            unsigned a[4], b[8][2];
            {
                int row  = rbase + (lq & 1)*8 + lr;
                int kcol = kd + (lq >> 1)*8;
                ldm_x4(a[0], a[1], a[2], a[3], qbase + (row*QW + kcol)*2);
            }
            #pragma unroll
            for (int np = 0; np < 4; np++) {
                int row  = np*16 + (lq >> 1)*8 + lr;
                int kcol = kd + (lq & 1)*8;
                ldm_x4(b[np*2][0], b[np*2][1], b[np*2+1][0], b[np*2+1][1],
                       kbase + (row*QW + kcol)*2);
            }
            #pragma unroll
            for (int nf = 0; nf < 8; nf++) mma_h(s[nf], a, b[nf]);
        }

        // online softmax
        #pragma unroll
        for (int half = 0; half < 2; half++) {
            float mx = -INFINITY;
            #pragma unroll
            for (int nf = 0; nf < 8; nf++)
                mx = fmaxf(mx, fmaxf(s[nf][half*2], s[nf][half*2+1]));
            mx *= scale;
            mx = fmaxf(mx, __shfl_xor_sync(0xffffffffu, mx, 1));
            mx = fmaxf(mx, __shfl_xor_sync(0xffffffffu, mx, 2));
            float m_new = fmaxf(m_i[half], mx);
            float corr  = __expf(m_i[half] - m_new);
            float lsum  = 0.f;
            #pragma unroll
            for (int nf = 0; nf < 8; nf++) {
                float p0 = __expf(s[nf][half*2]   * scale - m_new);
                float p1 = __expf(s[nf][half*2+1] * scale - m_new);
                s[nf][half*2]   = p0;
                s[nf][half*2+1] = p1;
                lsum += p0 + p1;
            }
            lsum += __shfl_xor_sync(0xffffffffu, lsum, 1);
            lsum += __shfl_xor_sync(0xffffffffu, lsum, 2);
            l_i[half] = l_i[half] * corr + lsum;
            m_i[half] = m_new;
            #pragma unroll
            for (int nf = 0; nf < 16; nf++) {
                o[nf][half*2]   *= corr;
                o[nf][half*2+1] *= corr;
            }
        }

        // P -> smem (fp16)
        __half* Pw = Ps + warp*16*PW;
        #pragma unroll
        for (int nf = 0; nf < 8; nf++) {
            int col = nf*8 + 2*t4;
            *(__half2*)&Pw[g*PW + col]     = __floats2half2_rn(s[nf][0], s[nf][1]);
            *(__half2*)&Pw[(g+8)*PW + col] = __floats2half2_rn(s[nf][2], s[nf][3]);
        }

        asm volatile("cp.async.wait_group 0;");   // V(kt) landed
        __syncthreads();

        // prefetch K(kt+1) under O-compute
        if (kt + 1 < Sc/64) {
            #pragma unroll
            for (int i = 0; i < 4; i++) {
                int c = tid + i*256;
                int row = c >> 4, kc = (c & 15) * 8;
                cp16(Ks + row*QW + kc, Kg + (size_t)(kt+1)*8192 + row*128 + kc);
            }
        }
        cp_commit();

        // O += P @ V
        #pragma unroll
        for (int ks = 0; ks < 4; ks++) {
            int kv = ks*16;
            unsigned a[4], b[16][2];
            {
                int row  = (lq & 1)*8 + lr;
                int kcol = kv + (lq >> 1)*8;
                ldm_x4(a[0], a[1], a[2], a[3], pbase + (row*PW + kcol)*2);
            }
            #pragma unroll
            for (int np = 0; np < 8; np++) {
                int row = kv + (lq & 1)*8 + lr;
                int col = np*16 + (lq >> 1)*8;
                ldm_x4_t(b[np*2][0], b[np*2][1], b[np*2+1][0], b[np*2+1][1],
                         vbase + (row*QW + col)*2);
            }
            #pragma unroll
            for (int nf = 0; nf < 16; nf++) mma_h(o[nf], a, b[nf]);
        }

        asm volatile("cp.async.wait_group 0;");   // K(kt+1) landed
        __syncthreads();
    }

    // epilogue: normalize, write fp16 to g_attn [b, s, h*128+d]
    int b = bh / Hc, h = bh % Hc;
    float inv0 = 1.f / l_i[0], inv1 = 1.f / l_i[1];
    #pragma unroll
    for (int nf = 0; nf < 16; nf++) {
        int d = nf*8 + 2*t4;
        int r0 = qb*128 + rbase + g;
        __half2* p0 = (__half2*)(g_attn + (((size_t)(b*Sc + r0)) << 11) + h*128 + d);
        *p0 = __floats2half2_rn(o[nf][0]*inv0, o[nf][1]*inv0);
        __half2* p1 = (__half2*)(g_attn + (((size_t)(b*Sc + r0 + 8)) << 11) + h*128 + d);
        *p1 = __floats2half2_rn(o[nf][2]*inv1, o[nf][3]*inv1);
    }
}

// ---------------------------------------------------------------------------
extern "C" void kernel_launch(void* const* d_in, const int* in_sizes, int n_in,
                              void* d_out, int out_size) {
    const float *x = nullptr, *wqkv = nullptr, *wout = nullptr;
    for (int i = 0; i < n_in; i++) {
        int sz = in_sizes[i];
        if (sz == Bc*Sc*Ec)     x    = (const float*)d_in[i];
        else if (sz == Ec*3*Ac) wqkv = (const float*)d_in[i];
        else if (sz == Ac*Ec)   wout = (const float*)d_in[i];
    }
    float* out = (float*)d_out;
    const int M = Bc * Sc;  // 4096

    cudaFuncSetAttribute(gemm_h,
        cudaFuncAttributeMaxDynamicSharedMemorySize, 3*STG_B);
    size_t fsmem = (size_t)(128*QW + 64*QW + 64*QW + 8*16*PW) * sizeof(__half);
    cudaFuncSetAttribute(flash_h,
        cudaFuncAttributeMaxDynamicSharedMemorySize, (int)fsmem);

    rope_table_kernel<<<(Sc*(HDc/2) + 255)/256, 256>>>();

    __half *dxh, *dwq, *dwo;
    cudaGetSymbolAddress((void**)&dxh, g_x_h);
    cudaGetSymbolAddress((void**)&dwq, g_wqkv_t);
    cudaGetSymbolAddress((void**)&dwo, g_wout_t);

    {
        int n4 = Bc*Sc*Ec/4;
        cvt_h<<<(n4+255)/256, 256>>>((const float4*)x, (__half2*)dxh, n4);
    }
    transpose_cvt_h<<<dim3(3*Ac/32, Ec/32), 256>>>(wqkv, dwq, Ec, 3*Ac);
    transpose_cvt_h<<<dim3(Ec/32,   Ac/32), 256>>>(wout, dwo, Ac, Ec);

    // QKV GEMM + RoPE scatter  (CTA 128x128, 4 warps, 2 CTAs/SM)
    gemm_h<<<dim3(3*Ac/128, M/128), 128, 3*STG_B>>>(nullptr, 3*Ac, Ec, 1);

    // Flash attention
    flash_h<<<dim3(Sc/128, Bc*Hc), 256, fsmem>>>();

    // Output projection
    gemm_h<<<dim3(Ec/128, M/128), 128, 3*STG_B>>>(out, Ec, Ac, 0);
}

// round 16
// speedup vs baseline: 1.2168x; 1.0343x over previous
#include <cuda_runtime.h>
#include <cuda_fp16.h>
#include <math.h>
#include <stdint.h>

#define Bc  2
#define Sc  2048
#define Ec  2048
#define Ac  2048
#define Hc  16
#define HDc 128

// Scratch (device globals), fp16 operands.
__device__ __half g_Q[Bc*Hc*Sc*HDc];
__device__ __half g_K[Bc*Hc*Sc*HDc];
__device__ __half g_V[Bc*Hc*Sc*HDc];
__device__ __half g_attn[Bc*Sc*Ac];          // attention out (fp16)
__device__ __half g_x_h[Bc*Sc*Ec];           // x fp16 [4096][2048]
__device__ __half g_wqkv_t[3*Ac*Ec];         // W_qkv^T fp16 [6144][2048]
__device__ __half g_wout_t[Ec*Ac];           // W_out^T fp16 [2048][2048]
__device__ float  g_cos[Sc*(HDc/2)];
__device__ float  g_sin[Sc*(HDc/2)];

// ---------------------------------------------------------------------------
__device__ __forceinline__ void mma_h(float* c, const unsigned* a, const unsigned* b) {
    asm volatile("mma.sync.aligned.m16n8k16.row.col.f32.f16.f16.f32 "
        "{%0,%1,%2,%3}, {%4,%5,%6,%7}, {%8,%9}, {%0,%1,%2,%3};"
        : "+f"(c[0]), "+f"(c[1]), "+f"(c[2]), "+f"(c[3])
        : "r"(a[0]), "r"(a[1]), "r"(a[2]), "r"(a[3]), "r"(b[0]), "r"(b[1]));
}
__device__ __forceinline__ void ldm_x4(unsigned& r0, unsigned& r1, unsigned& r2,
                                       unsigned& r3, unsigned addr) {
    asm volatile("ldmatrix.sync.aligned.m8n8.x4.shared.b16 {%0,%1,%2,%3}, [%4];"
        : "=r"(r0), "=r"(r1), "=r"(r2), "=r"(r3) : "r"(addr));
}
__device__ __forceinline__ void ldm_x4_t(unsigned& r0, unsigned& r1, unsigned& r2,
                                         unsigned& r3, unsigned addr) {
    asm volatile("ldmatrix.sync.aligned.m8n8.x4.trans.shared.b16 {%0,%1,%2,%3}, [%4];"
        : "=r"(r0), "=r"(r1), "=r"(r2), "=r"(r3) : "r"(addr));
}
__device__ __forceinline__ void cp16(void* smem_dst, const void* gsrc) {
    unsigned d = (unsigned)__cvta_generic_to_shared(smem_dst);
    asm volatile("cp.async.cg.shared.global [%0], [%1], 16;" :: "r"(d), "l"(gsrc));
}
__device__ __forceinline__ void cp_commit() { asm volatile("cp.async.commit_group;"); }
__device__ __forceinline__ unsigned smem_u32(const void* p) {
    return (unsigned)__cvta_generic_to_shared(p);
}
__device__ __forceinline__ unsigned packh2(float x, float y) {
    __half2 h = __floats2half2_rn(x, y);
    return *reinterpret_cast<unsigned*>(&h);
}

// ---------------------------------------------------------------------------
__global__ void rope_table_kernel() {
    int idx = blockIdx.x * blockDim.x + threadIdx.x;
    if (idx >= Sc * (HDc/2)) return;
    int pos = idx / (HDc/2);
    int j   = idx % (HDc/2);
    double inv = pow(10000.0, -((double)(2*j)) / (double)HDc);
    double a = (double)pos * inv;
    g_cos[idx] = (float)cos(a);
    g_sin[idx] = (float)sin(a);
}

__global__ void cvt_h(const float4* __restrict__ src, __half2* __restrict__ dst, int n4) {
    int i = blockIdx.x * blockDim.x + threadIdx.x;
    if (i < n4) {
        float4 v = src[i];
        dst[2*i]   = __floats2half2_rn(v.x, v.y);
        dst[2*i+1] = __floats2half2_rn(v.z, v.w);
    }
}

__global__ __launch_bounds__(256) void transpose_cvt_h(
    const float* __restrict__ src, __half* __restrict__ dst, int R, int Ccols) {
    __shared__ __half tile[32][33];
    int c0 = blockIdx.x*32, r0 = blockIdx.y*32;
    int tx = threadIdx.x & 31, ty = threadIdx.x >> 5;
    #pragma unroll
    for (int i = 0; i < 4; i++)
        tile[ty + 8*i][tx] = __float2half(src[(size_t)(r0 + ty + 8*i)*Ccols + c0 + tx]);
    __syncthreads();
    #pragma unroll
    for (int i = 0; i < 4; i++)
        dst[(size_t)(c0 + ty + 8*i)*R + r0 + tx] = tile[tx][ty + 8*i];
}

// ---------------------------------------------------------------------------
// fp16 GEMM (R15 winning config): CTA 128x128, BK=32, 4 warps (2x2), warp
// tile 64x64, 3-stage cp.async, ldmatrix, 128 threads, 2 CTAs/SM.
// mode 1: A=g_x_h, B=g_wqkv_t -> RoPE scatter to g_Q/g_K/g_V.
// mode 0: A=g_attn, B=g_wout_t -> fp32 C.
// ---------------------------------------------------------------------------
#define AW 40                         // padded row width (halves)
#define STG_H (2*128*AW)              // halves per stage (A+B)
#define STG_B (STG_H*2)               // bytes per stage (20480)

__global__ __launch_bounds__(128, 2) void gemm_h(
    float* __restrict__ C, int N, int K, int mode)
{
    extern __shared__ __half hs[];

    const __half* Ag = mode ? g_x_h : g_attn;
    const __half* Bg = mode ? g_wqkv_t : g_wout_t;

    int tid  = threadIdx.x;
    int warp = tid >> 5, lane = tid & 31;
    int lr = lane & 7, lq = lane >> 3;
    int g = lane >> 2, t4 = lane & 3;
    int wm = warp >> 1, wn = warp & 1;          // 2x2 warp grid, 64x64 tiles
    int m0 = blockIdx.y * 128, n0 = blockIdx.x * 128;
    unsigned sbase = smem_u32(hs);

    float acc[4][8][4];
    #pragma unroll
    for (int i = 0; i < 4; i++)
        #pragma unroll
        for (int j = 0; j < 8; j++)
            #pragma unroll
            for (int r = 0; r < 4; r++) acc[i][j][r] = 0.f;

    int T = K / 32;

    auto load_stage = [&](int s, int kt) {
        __half* As = hs + s*STG_H;
        __half* Bs = As + 128*AW;
        #pragma unroll
        for (int i = 0; i < 4; i++) {
            int c = tid + i*128;
            int row = c >> 2, kc = (c & 3) * 8;
            cp16(As + row*AW + kc, Ag + (size_t)(m0+row)*K + kt*32 + kc);
            cp16(Bs + row*AW + kc, Bg + (size_t)(n0+row)*K + kt*32 + kc);
        }
        cp_commit();
    };

    load_stage(0, 0);
    load_stage(1, 1);

    for (int it = 0; it < T; it++) {
        asm volatile("cp.async.wait_group 1;");
        __syncthreads();
        if (it + 2 < T) load_stage((it+2) % 3, it+2);
        else cp_commit();

        unsigned abase = sbase + (it % 3) * STG_B;
        unsigned bbase = abase + 128*AW*2;

        #pragma unroll
        for (int kk = 0; kk < 32; kk += 16) {
            unsigned a[4][4], b[8][2];
            #pragma unroll
            for (int mf = 0; mf < 4; mf++) {
                int row  = wm*64 + mf*16 + (lq & 1)*8 + lr;
                int kcol = kk + (lq >> 1)*8;
                ldm_x4(a[mf][0], a[mf][1], a[mf][2], a[mf][3],
                       abase + (row*AW + kcol)*2);
            }
            #pragma unroll
            for (int np = 0; np < 4; np++) {
                int row  = wn*64 + np*16 + (lq >> 1)*8 + lr;
                int kcol = kk + (lq & 1)*8;
                ldm_x4(b[np*2][0], b[np*2][1], b[np*2+1][0], b[np*2+1][1],
                       bbase + (row*AW + kcol)*2);
            }
            #pragma unroll
            for (int mf = 0; mf < 4; mf++)
                #pragma unroll
                for (int nf = 0; nf < 8; nf++)
                    mma_h(acc[mf][nf], a[mf], b[nf]);
        }
    }

    if (mode == 0) {
        #pragma unroll
        for (int mf = 0; mf < 4; mf++)
            #pragma unroll
            for (int nf = 0; nf < 8; nf++) {
                int row = m0 + wm*64 + mf*16 + g;
                int col = n0 + wn*64 + nf*8 + 2*t4;
                *(float2*)(C + (size_t)row*N + col) =
                    make_float2(acc[mf][nf][0], acc[mf][nf][1]);
                *(float2*)(C + (size_t)(row+8)*N + col) =
                    make_float2(acc[mf][nf][2], acc[mf][nf][3]);
            }
    } else {
        #pragma unroll
        for (int nf = 0; nf < 8; nf++) {
            int n   = n0 + wn*64 + nf*8 + 2*t4;
            int t   = n / 2048;
            int rem = n % 2048;
            int h   = rem >> 7;
            int d   = rem & 127;
            int j   = d >> 1;
            __half* dst = (t == 0) ? g_Q : (t == 1) ? g_K : g_V;
            #pragma unroll
            for (int mf = 0; mf < 4; mf++) {
                #pragma unroll
                for (int half = 0; half < 2; half++) {
                    int row = m0 + wm*64 + mf*16 + g + half*8;
                    int b = row >> 11, s = row & 2047;
                    float c0 = acc[mf][nf][half*2];
                    float c1 = acc[mf][nf][half*2 + 1];
                    __half2* p = (__half2*)(dst
                        + (((size_t)(b*Hc + h)*Sc + s) << 7) + d);
                    if (t == 2) *p = __floats2half2_rn(c0, c1);
                    else {
                        float cs = g_cos[s*64 + j], sn = g_sin[s*64 + j];
                        *p = __floats2half2_rn(c0*cs - c1*sn, c0*sn + c1*cs);
                    }
                }
            }
        }
    }
}

// ---------------------------------------------------------------------------
// fp16 flash attention. BM=128, BN=64, 256 threads (8 warps x 16 q-rows).
// R16: Q fragments hoisted out of the KV loop (loaded once); S accumulator
// reused directly as the PV A operand (no P smem slab, no P ldmatrix).
// ---------------------------------------------------------------------------
#define QW 136

__global__ __launch_bounds__(256, 1) void flash_h() {
    extern __shared__ __half sh[];
    __half* Qs = sh;                   // [128][136]
    __half* Ks = Qs + 128*QW;          // [64][136]
    __half* Vs = Ks + 64*QW;           // [64][136]

    int tid  = threadIdx.x;
    int warp = tid >> 5, lane = tid & 31;
    int lr = lane & 7, lq = lane >> 3;
    int g = lane >> 2, t4 = lane & 3;
    int qb = blockIdx.x, bh = blockIdx.y;

    const __half* Qg = g_Q + (((size_t)bh*Sc + qb*128) << 7);
    const __half* Kg = g_K + ((size_t)bh*Sc << 7);
    const __half* Vg = g_V + ((size_t)bh*Sc << 7);

    unsigned qbase = smem_u32(Qs);
    unsigned kbase = smem_u32(Ks);
    unsigned vbase = smem_u32(Vs);

    #pragma unroll
    for (int i = 0; i < 8; i++) {
        int c = tid + i*256;
        int row = c >> 4, kc = (c & 15) * 8;
        cp16(Qs + row*QW + kc, Qg + row*128 + kc);
    }
    #pragma unroll
    for (int i = 0; i < 4; i++) {
        int c = tid + i*256;
        int row = c >> 4, kc = (c & 15) * 8;
        cp16(Ks + row*QW + kc, Kg + row*128 + kc);
    }
    cp_commit();

    float m_i[2] = {-INFINITY, -INFINITY}, l_i[2] = {0.f, 0.f};
    float o[16][4];
    #pragma unroll
    for (int nf = 0; nf < 16; nf++)
        #pragma unroll
        for (int r = 0; r < 4; r++) o[nf][r] = 0.f;

    const float scale = 0.08838834764831845f;
    int rbase = warp * 16;

    asm volatile("cp.async.wait_group 0;");
    __syncthreads();

    // Hoist Q fragments (invariant across the whole KV loop)
    unsigned aq[8][4];
    #pragma unroll
    for (int ks = 0; ks < 8; ks++) {
        int row  = rbase + (lq & 1)*8 + lr;
        int kcol = ks*16 + (lq >> 1)*8;
        ldm_x4(aq[ks][0], aq[ks][1], aq[ks][2], aq[ks][3],
               qbase + (row*QW + kcol)*2);
    }

    for (int kt = 0; kt < Sc/64; kt++) {
        // prefetch V(kt) under S-compute
        #pragma unroll
        for (int i = 0; i < 4; i++) {
            int c = tid + i*256;
            int row = c >> 4, kc = (c & 15) * 8;
            cp16(Vs + row*QW + kc, Vg + (size_t)kt*8192 + row*128 + kc);
        }
        cp_commit();

        // S = Q @ K^T
        float s[8][4];
        #pragma unroll
        for (int nf = 0; nf < 8; nf++)
            #pragma unroll
            for (int r = 0; r < 4; r++) s[nf][r] = 0.f;

        #pragma unroll
        for (int ks = 0; ks < 8; ks++) {
            int kd = ks*16;
            unsigned b[8][2];
            #pragma unroll
            for (int np = 0; np < 4; np++) {
                int row  = np*16 + (lq >> 1)*8 + lr;
                int kcol = kd + (lq & 1)*8;
                ldm_x4(b[np*2][0], b[np*2][1], b[np*2+1][0], b[np*2+1][1],
                       kbase + (row*QW + kcol)*2);
            }
            #pragma unroll
            for (int nf = 0; nf < 8; nf++) mma_h(s[nf], aq[ks], b[nf]);
        }

        // online softmax
        #pragma unroll
        for (int half = 0; half < 2; half++) {
            float mx = -INFINITY;
            #pragma unroll
            for (int nf = 0; nf < 8; nf++)
                mx = fmaxf(mx, fmaxf(s[nf][half*2], s[nf][half*2+1]));
            mx *= scale;
            mx = fmaxf(mx, __shfl_xor_sync(0xffffffffu, mx, 1));
            mx = fmaxf(mx, __shfl_xor_sync(0xffffffffu, mx, 2));
            float m_new = fmaxf(m_i[half], mx);
            float corr  = __expf(m_i[half] - m_new);
            float lsum  = 0.f;
            #pragma unroll
            for (int nf = 0; nf < 8; nf++) {
                float p0 = __expf(s[nf][half*2]   * scale - m_new);
                float p1 = __expf(s[nf][half*2+1] * scale - m_new);
                s[nf][half*2]   = p0;
                s[nf][half*2+1] = p1;
                lsum += p0 + p1;
            }
            lsum += __shfl_xor_sync(0xffffffffu, lsum, 1);
            lsum += __shfl_xor_sync(0xffffffffu, lsum, 2);
            l_i[half] = l_i[half] * corr + lsum;
            m_i[half] = m_new;
            #pragma unroll
            for (int nf = 0; nf < 16; nf++) {
                o[nf][half*2]   *= corr;
                o[nf][half*2+1] *= corr;
            }
        }

        // Pack S accumulator directly into PV A-fragments (no smem roundtrip).
        // a0=P[g][2t4,+1], a1=P[g+8][2t4,+1], a2=P[g][2t4+8,+1], a3=P[g+8][2t4+8,+1]
        unsigned pa[4][4];
        #pragma unroll
        for (int ks = 0; ks < 4; ks++) {
            pa[ks][0] = packh2(s[2*ks][0],   s[2*ks][1]);
            pa[ks][1] = packh2(s[2*ks][2],   s[2*ks][3]);
            pa[ks][2] = packh2(s[2*ks+1][0], s[2*ks+1][1]);
            pa[ks][3] = packh2(s[2*ks+1][2], s[2*ks+1][3]);
        }

        asm volatile("cp.async.wait_group 0;");   // V(kt) landed
        __syncthreads();

        // prefetch K(kt+1) under O-compute
        if (kt + 1 < Sc/64) {
            #pragma unroll
            for (int i = 0; i < 4; i++) {
                int c = tid + i*256;
                int row = c >> 4, kc = (c & 15) * 8;
                cp16(Ks + row*QW + kc, Kg + (size_t)(kt+1)*8192 + row*128 + kc);
            }
        }
        cp_commit();

        // O += P @ V
        #pragma unroll
        for (int ks = 0; ks < 4; ks++) {
            int kv = ks*16;
            unsigned b[16][2];
            #pragma unroll
            for (int np = 0; np < 8; np++) {
                int row = kv + (lq & 1)*8 + lr;
                int col = np*16 + (lq >> 1)*8;
                ldm_x4_t(b[np*2][0], b[np*2][1], b[np*2+1][0], b[np*2+1][1],
                         vbase + (row*QW + col)*2);
            }
            #pragma unroll
            for (int nf = 0; nf < 16; nf++) mma_h(o[nf], pa[ks], b[nf]);
        }

        asm volatile("cp.async.wait_group 0;");   // K(kt+1) landed
        __syncthreads();
    }

    // epilogue: normalize, write fp16 to g_attn [b, s, h*128+d]
    int b = bh / Hc, h = bh % Hc;
    float inv0 = 1.f / l_i[0], inv1 = 1.f / l_i[1];
    #pragma unroll
    for (int nf = 0; nf < 16; nf++) {
        int d = nf*8 + 2*t4;
        int r0 = qb*128 + rbase + g;
        __half2* p0 = (__half2*)(g_attn + (((size_t)(b*Sc + r0)) << 11) + h*128 + d);
        *p0 = __floats2half2_rn(o[nf][0]*inv0, o[nf][1]*inv0);
        __half2* p1 = (__half2*)(g_attn + (((size_t)(b*Sc + r0 + 8)) << 11) + h*128 + d);
        *p1 = __floats2half2_rn(o[nf][2]*inv1, o[nf][3]*inv1);
    }
}

// ---------------------------------------------------------------------------
extern "C" void kernel_launch(void* const* d_in, const int* in_sizes, int n_in,
                              void* d_out, int out_size) {
    const float *x = nullptr, *wqkv = nullptr, *wout = nullptr;
    for (int i = 0; i < n_in; i++) {
        int sz = in_sizes[i];
        if (sz == Bc*Sc*Ec)     x    = (const float*)d_in[i];
        else if (sz == Ec*3*Ac) wqkv = (const float*)d_in[i];
        else if (sz == Ac*Ec)   wout = (const float*)d_in[i];
    }
    float* out = (float*)d_out;
    const int M = Bc * Sc;  // 4096

    cudaFuncSetAttribute(gemm_h,
        cudaFuncAttributeMaxDynamicSharedMemorySize, 3*STG_B);
    size_t fsmem = (size_t)(128*QW + 64*QW + 64*QW) * sizeof(__half);
    cudaFuncSetAttribute(flash_h,
        cudaFuncAttributeMaxDynamicSharedMemorySize, (int)fsmem);

    rope_table_kernel<<<(Sc*(HDc/2) + 255)/256, 256>>>();

    __half *dxh, *dwq, *dwo;
    cudaGetSymbolAddress((void**)&dxh, g_x_h);
    cudaGetSymbolAddress((void**)&dwq, g_wqkv_t);
    cudaGetSymbolAddress((void**)&dwo, g_wout_t);

    {
        int n4 = Bc*Sc*Ec/4;
        cvt_h<<<(n4+255)/256, 256>>>((const float4*)x, (__half2*)dxh, n4);
    }
    transpose_cvt_h<<<dim3(3*Ac/32, Ec/32), 256>>>(wqkv, dwq, Ec, 3*Ac);
    transpose_cvt_h<<<dim3(Ec/32,   Ac/32), 256>>>(wout, dwo, Ac, Ec);

    // QKV GEMM + RoPE scatter  (CTA 128x128, 4 warps, 2 CTAs/SM)
    gemm_h<<<dim3(3*Ac/128, M/128), 128, 3*STG_B>>>(nullptr, 3*Ac, Ec, 1);

    // Flash attention
    flash_h<<<dim3(Sc/128, Bc*Hc), 256, fsmem>>>();

    // Output projection
    gemm_h<<<dim3(Ec/128, M/128), 128, 3*STG_B>>>(out, Ec, Ac, 0);
}